// round 13
// baseline (speedup 1.0000x reference)
#include <cuda_runtime.h>
#include <cstdint>

// Problem constants (fixed by setup_inputs)
#define B_ 16
#define A_ 9
#define H_ 128
#define W_ 128
#define S_ 2048.0f
// sigmoid(d) > 0.7  <=>  d > ln(7/3)
#define LOGIT_THRESH 0.84729786038720363f

#define TPB 128
#define NTILES (B_ * A_ * H_ * (W_ / 4) / TPB)   // 4608 tiles of 128 vec-groups
#define GRID 768                                 // persistent blocks; 6 tiles each
#define TILE_BYTES (TPB * 9 * 16)                // 18432 B output per tile

// Precomputed anchor table, (a, w) order: (acx, acy, aw, ah). 18 KB, L1/L2-hot.
// (per-block a*w*129 gather is lane-divergent: ~9us, measured R4 vs R5;
//  fused-prologue spin: +5us, measured R12. Two launches is the optimum.)
__device__ float4 d_anc_tab[A_ * W_];

__global__ void build_anchor_tab(const float* __restrict__ anchor) {
    int t = blockIdx.x * blockDim.x + threadIdx.x;
    if (t >= A_ * W_) return;
    int a = t / W_;
    int w = t % W_;
    long row = (long)a * w * (W_ + 1);    // idx[a,w] = a*w*(W+1)
    const float* p = anchor + row * 6;
    d_anc_tab[t] = make_float4(p[2], p[3], p[4], p[5]);
}

__device__ __forceinline__ uint32_t smem_u32(const void* p) {
    uint32_t a;
    asm("{ .reg .u64 t; cvta.to.shared.u64 t, %1; cvt.u32.u64 %0, t; }"
        : "=r"(a) : "l"(p));
    return a;
}

// Persistent grid-stride kernel with ping-pong smem buffers:
// tile k's TMA store drains while tile k+1 computes, so the DRAM write
// stream is fed continuously instead of in end-of-block bursts (R9's tail).
// wait_group.read 1 before reusing a buffer guarantees the store issued two
// iterations earlier has finished READING that buffer.
__global__ __launch_bounds__(TPB) void proposal_kernel(
    const float* __restrict__ cla,
    const float* __restrict__ reg,
    float* __restrict__ out)
{
    __shared__ __align__(128) float4 sOut[2][TPB * 9];   // 2 x 18432 B

    const int WQ  = W_ / 4;         // 32
    const int HW4 = (H_ * W_) / 4;  // 4096 float4 per channel plane

    int tid = threadIdx.x;
    const float4* cla4 = (const float4*)cla;
    const float4* reg4 = (const float4*)reg;

    int nbuf = 0;
    #pragma unroll 1
    for (int tile = blockIdx.x; tile < NTILES; tile += GRID, nbuf ^= 1) {
        int t = tile * TPB + tid;
        int wq = t & (WQ - 1);                    // == tid & 31
        int h  = (t / WQ) & (H_ - 1);
        int a  = (t / (WQ * H_)) % A_;
        int b  =  t / (WQ * H_ * A_);
        int w0 = wq * 4;

        int sp4 = (h * W_ + w0) >> 2;

        int cbase = (b * 2 * A_ + 2 * a) * HW4 + sp4;
        float4 v_c0 = cla4[cbase];
        float4 v_c1 = cla4[cbase + HW4];

        int rbase = (b * 4 * A_ + 4 * a) * HW4 + sp4;
        float4 v_tx = reg4[rbase + 0 * HW4];
        float4 v_ty = reg4[rbase + 1 * HW4];
        float4 v_tw = reg4[rbase + 2 * HW4];
        float4 v_th = reg4[rbase + 3 * HW4];

        // Anchor entries: lane-consecutive coalesced from the L1-hot table.
        const float4* tab = d_anc_tab + a * W_ + w0;
        float4 anca[4] = {tab[0], tab[1], tab[2], tab[3]};

        float c0a[4] = {v_c0.x, v_c0.y, v_c0.z, v_c0.w};
        float c1a[4] = {v_c1.x, v_c1.y, v_c1.z, v_c1.w};
        float txa[4] = {v_tx.x, v_tx.y, v_tx.z, v_tx.w};
        float tya[4] = {v_ty.x, v_ty.y, v_ty.z, v_ty.w};
        float twa[4] = {v_tw.x, v_tw.y, v_tw.z, v_tw.w};
        float tha[4] = {v_th.x, v_th.y, v_th.z, v_th.w};

        float4* my = sOut[nbuf] + tid * 9;   // stride 36 words: conflict-free STS.128

        float f[4][9];
        #pragma unroll
        for (int i = 0; i < 4; i++) {
            float acx = anca[i].x, acy = anca[i].y, aw = anca[i].z, ah = anca[i].w;

            float cxn = fmaf(txa[i], aw, acx);
            float cyn = fmaf(tya[i], ah, acy);
            float wvn = expf(twa[i]) * aw;
            float hvn = expf(tha[i]) * ah;

            float ltxn = cxn - 0.5f * wvn;
            float ltyn = cyn - 0.5f * hvn;
            float rbxn = cxn + 0.5f * wvn;
            float rbyn = cyn + 0.5f * hvn;

            // fg > 0.7  <=>  (c1 - c0) > ln(7/3)
            bool valid = ((c1a[i] - c0a[i]) > LOGIT_THRESH)
                         && (ltxn >= 0.0f) && (ltyn >= 0.0f)
                         && (rbxn <= 1.0f) && (rbyn <= 1.0f);
            float m = valid ? 1.0f : 0.0f;

            f[i][0] = (ltxn * S_) * m;
            f[i][1] = (ltyn * S_) * m;
            f[i][2] = (rbxn * S_) * m;
            f[i][3] = (rbyn * S_) * m;
            f[i][4] = cxn * m;
            f[i][5] = cyn * m;
            f[i][6] = wvn * m;
            f[i][7] = hvn * m;
            f[i][8] = m;
        }

        // Pack 4x9 floats into 9 float4 smem slots (output-linear order).
        my[0] = make_float4(f[0][0], f[0][1], f[0][2], f[0][3]);
        my[1] = make_float4(f[0][4], f[0][5], f[0][6], f[0][7]);
        my[2] = make_float4(f[0][8], f[1][0], f[1][1], f[1][2]);
        my[3] = make_float4(f[1][3], f[1][4], f[1][5], f[1][6]);
        my[4] = make_float4(f[1][7], f[1][8], f[2][0], f[2][1]);
        my[5] = make_float4(f[2][2], f[2][3], f[2][4], f[2][5]);
        my[6] = make_float4(f[2][6], f[2][7], f[2][8], f[3][0]);
        my[7] = make_float4(f[3][1], f[3][2], f[3][3], f[3][4]);
        my[8] = make_float4(f[3][5], f[3][6], f[3][7], f[3][8]);

        __syncthreads();           // buffer nbuf fully written

        if (tid == 0) {
            asm volatile("fence.proxy.async.shared::cta;" ::: "memory");
            uint32_t src = smem_u32(sOut[nbuf]);
            float* dst = out + (size_t)tile * (TPB * 36);
            asm volatile(
                "cp.async.bulk.global.shared::cta.bulk_group [%0], [%1], %2;"
                :: "l"(dst), "r"(src), "r"((int)TILE_BYTES) : "memory");
            asm volatile("cp.async.bulk.commit_group;" ::: "memory");
            // allow 1 group in flight; the store issued 2 iters ago (same
            // buffer as next iteration) is guaranteed drained after this.
            asm volatile("cp.async.bulk.wait_group.read 1;" ::: "memory");
        }
        __syncthreads();           // nobody overwrites the other buffer early
    }

    // Drain remaining stores before smem is released.
    if (tid == 0) {
        asm volatile("cp.async.bulk.wait_group.read 0;" ::: "memory");
    }
    __syncthreads();
}

extern "C" void kernel_launch(void* const* d_in, const int* in_sizes, int n_in,
                              void* d_out, int out_size) {
    const float* cla    = (const float*)d_in[0];
    const float* reg    = (const float*)d_in[1];
    const float* anchor = (const float*)d_in[2];
    float* out = (float*)d_out;

    build_anchor_tab<<<(A_ * W_ + 127) / 128, 128>>>(anchor);
    proposal_kernel<<<GRID, TPB>>>(cla, reg, out);
}

// round 14
// speedup vs baseline: 1.0107x; 1.0107x over previous
#include <cuda_runtime.h>
#include <cstdint>

// Problem constants (fixed by setup_inputs)
#define B_ 16
#define A_ 9
#define H_ 128
#define W_ 128
#define S_ 2048.0f
// sigmoid(d) > 0.7  <=>  d > ln(7/3)
#define LOGIT_THRESH 0.84729786038720363f

#define TPB 128
#define BLK_BYTES (TPB * 9 * 16)   // 18432 B contiguous output per block

// Precomputed anchor table, (a, w) order: (acx, acy, aw, ah). 18 KB, L1/L2-hot.
// (per-block a*w*129 gather is lane-divergent: ~9us, measured R4 vs R5;
//  fused-prologue spin: +5us, measured R12. Two launches is the optimum.)
__device__ float4 d_anc_tab[A_ * W_];

__global__ void build_anchor_tab(const float* __restrict__ anchor) {
    int t = blockIdx.x * blockDim.x + threadIdx.x;
    if (t >= A_ * W_) return;
    int a = t / W_;
    int w = t % W_;
    long row = (long)a * w * (W_ + 1);    // idx[a,w] = a*w*(W+1)
    const float* p = anchor + row * 6;
    d_anc_tab[t] = make_float4(p[2], p[3], p[4], p[5]);
}

__device__ __forceinline__ uint32_t smem_u32(const void* p) {
    uint32_t a;
    asm("{ .reg .u64 t; cvta.to.shared.u64 t, %1; cvt.u32.u64 %0, t; }"
        : "=r"(a) : "l"(p));
    return a;
}

// R9 structure (best measured: 20.5us main / 28.7us total): one-shot blocks,
// compute -> smem pack -> single TMA 1-D bulk store per block.
// R14 adds only the max-smem carveout hint so ~11-12 blocks can co-reside
// (18.4KB x 12 = 221KB <= 228KB); default carveout capped residency at ~7.
__global__ __launch_bounds__(TPB) void proposal_kernel(
    const float* __restrict__ cla,
    const float* __restrict__ reg,
    float* __restrict__ out)
{
    // Output staging: TPB threads x 9 float4 slots, output-linear layout.
    __shared__ __align__(128) float4 sOut[TPB * 9];   // 18432 B

    const int WQ  = W_ / 4;         // 32
    const int HW4 = (H_ * W_) / 4;  // 4096 float4 per channel plane

    int tid = threadIdx.x;
    int t = blockIdx.x * TPB + tid;
    int wq = t & (WQ - 1);                    // == tid & 31
    int h  = (t / WQ) & (H_ - 1);
    int a  = (t / (WQ * H_)) % A_;            // uniform within a block
    int b  =  t / (WQ * H_ * A_);
    int w0 = wq * 4;

    int sp4 = (h * W_ + w0) >> 2;

    const float4* cla4 = (const float4*)cla;
    const float4* reg4 = (const float4*)reg;

    int cbase = (b * 2 * A_ + 2 * a) * HW4 + sp4;
    float4 v_c0 = cla4[cbase];
    float4 v_c1 = cla4[cbase + HW4];

    int rbase = (b * 4 * A_ + 4 * a) * HW4 + sp4;
    float4 v_tx = reg4[rbase + 0 * HW4];
    float4 v_ty = reg4[rbase + 1 * HW4];
    float4 v_tw = reg4[rbase + 2 * HW4];
    float4 v_th = reg4[rbase + 3 * HW4];

    // Anchor entries: 4 consecutive float4s, lane-consecutive (L1-hot table).
    const float4* tab = d_anc_tab + a * W_ + w0;
    float4 anca[4] = {tab[0], tab[1], tab[2], tab[3]};

    float c0a[4] = {v_c0.x, v_c0.y, v_c0.z, v_c0.w};
    float c1a[4] = {v_c1.x, v_c1.y, v_c1.z, v_c1.w};
    float txa[4] = {v_tx.x, v_tx.y, v_tx.z, v_tx.w};
    float tya[4] = {v_ty.x, v_ty.y, v_ty.z, v_ty.w};
    float twa[4] = {v_tw.x, v_tw.y, v_tw.z, v_tw.w};
    float tha[4] = {v_th.x, v_th.y, v_th.z, v_th.w};

    float4* my = sOut + tid * 9;   // stride 36 words: conflict-free STS.128

    float f[4][9];
    #pragma unroll
    for (int i = 0; i < 4; i++) {
        float acx = anca[i].x, acy = anca[i].y, aw = anca[i].z, ah = anca[i].w;

        float cxn = fmaf(txa[i], aw, acx);
        float cyn = fmaf(tya[i], ah, acy);
        float wvn = expf(twa[i]) * aw;
        float hvn = expf(tha[i]) * ah;

        float ltxn = cxn - 0.5f * wvn;
        float ltyn = cyn - 0.5f * hvn;
        float rbxn = cxn + 0.5f * wvn;
        float rbyn = cyn + 0.5f * hvn;

        // fg > 0.7  <=>  (c1 - c0) > ln(7/3)
        bool valid = ((c1a[i] - c0a[i]) > LOGIT_THRESH)
                     && (ltxn >= 0.0f) && (ltyn >= 0.0f)
                     && (rbxn <= 1.0f) && (rbyn <= 1.0f);
        float m = valid ? 1.0f : 0.0f;

        f[i][0] = (ltxn * S_) * m;
        f[i][1] = (ltyn * S_) * m;
        f[i][2] = (rbxn * S_) * m;
        f[i][3] = (rbyn * S_) * m;
        f[i][4] = cxn * m;
        f[i][5] = cyn * m;
        f[i][6] = wvn * m;
        f[i][7] = hvn * m;
        f[i][8] = m;
    }

    // Pack 4x9 floats into 9 float4 smem slots (output-linear order).
    my[0] = make_float4(f[0][0], f[0][1], f[0][2], f[0][3]);
    my[1] = make_float4(f[0][4], f[0][5], f[0][6], f[0][7]);
    my[2] = make_float4(f[0][8], f[1][0], f[1][1], f[1][2]);
    my[3] = make_float4(f[1][3], f[1][4], f[1][5], f[1][6]);
    my[4] = make_float4(f[1][7], f[1][8], f[2][0], f[2][1]);
    my[5] = make_float4(f[2][2], f[2][3], f[2][4], f[2][5]);
    my[6] = make_float4(f[2][6], f[2][7], f[2][8], f[3][0]);
    my[7] = make_float4(f[3][1], f[3][2], f[3][3], f[3][4]);
    my[8] = make_float4(f[3][5], f[3][6], f[3][7], f[3][8]);

    __syncthreads();

    // Single TMA 1-D bulk store of the block's contiguous 18432B output.
    if (tid == 0) {
        asm volatile("fence.proxy.async.shared::cta;" ::: "memory");
        uint32_t src = smem_u32(sOut);
        float* dst = out + (size_t)blockIdx.x * (TPB * 36);
        asm volatile(
            "cp.async.bulk.global.shared::cta.bulk_group [%0], [%1], %2;"
            :: "l"(dst), "r"(src), "r"((int)BLK_BYTES) : "memory");
        asm volatile("cp.async.bulk.commit_group;" ::: "memory");
        asm volatile("cp.async.bulk.wait_group.read 0;" ::: "memory");
    }
}

extern "C" void kernel_launch(void* const* d_in, const int* in_sizes, int n_in,
                              void* d_out, int out_size) {
    const float* cla    = (const float*)d_in[0];
    const float* reg    = (const float*)d_in[1];
    const float* anchor = (const float*)d_in[2];
    float* out = (float*)d_out;

    // Request max-smem carveout so up to 12 x 18.4KB blocks co-reside per SM.
    // Idempotent host call; capture-legal (no allocation, no sync).
    cudaFuncSetAttribute(proposal_kernel,
                         cudaFuncAttributePreferredSharedMemoryCarveout, 100);

    build_anchor_tab<<<(A_ * W_ + 127) / 128, 128>>>(anchor);

    int total_vec = B_ * A_ * H_ * (W_ / 4);   // 589824
    proposal_kernel<<<total_vec / TPB, TPB>>>(cla, reg, out);
}

// round 15
// speedup vs baseline: 1.0781x; 1.0667x over previous
#include <cuda_runtime.h>
#include <cstdint>

// Problem constants (fixed by setup_inputs)
#define B_ 16
#define A_ 9
#define H_ 128
#define W_ 128
#define S_ 2048.0f
// sigmoid(d) > 0.7  <=>  d > ln(7/3)
#define LOGIT_THRESH 0.84729786038720363f

#define TPB 256
#define HALF_BYTES (128 * 9 * 16)   // 18432 B per half-block output

// Precomputed anchor table, (a, w) order: (acx, acy, aw, ah). 18 KB, L1/L2-hot.
// (per-block a*w*129 gather is lane-divergent: ~9us, measured R4 vs R5;
//  fused-prologue spin: +5us, measured R12. Two launches is the optimum.)
__device__ float4 d_anc_tab[A_ * W_];

__global__ void build_anchor_tab(const float* __restrict__ anchor) {
    int t = blockIdx.x * blockDim.x + threadIdx.x;
    if (t >= A_ * W_) return;
    int a = t / W_;
    int w = t % W_;
    long row = (long)a * w * (W_ + 1);    // idx[a,w] = a*w*(W+1)
    const float* p = anchor + row * 6;
    d_anc_tab[t] = make_float4(p[2], p[3], p[4], p[5]);
}

__device__ __forceinline__ uint32_t smem_u32(const void* p) {
    uint32_t a;
    asm("{ .reg .u64 t; cvta.to.shared.u64 t, %1; cvt.u32.u64 %0, t; }"
        : "=r"(a) : "l"(p));
    return a;
}

// R9 per-thread code at TPB=256: half the grid (less block churn), 100%
// theoretical residency (6 blocks x 256 = 1536 thr/SM), and two independent
// 18432B TMA bulk stores per block (tid 0 and tid 1 each own a bulk group,
// so the two halves drain in parallel).
__global__ __launch_bounds__(TPB) void proposal_kernel(
    const float* __restrict__ cla,
    const float* __restrict__ reg,
    float* __restrict__ out)
{
    // Output staging: TPB threads x 9 float4 slots, output-linear layout.
    __shared__ __align__(128) float4 sOut[TPB * 9];   // 36864 B (static, <=48KB)

    const int WQ  = W_ / 4;         // 32
    const int HW4 = (H_ * W_) / 4;  // 4096 float4 per channel plane

    int tid = threadIdx.x;
    int t = blockIdx.x * TPB + tid;
    int wq = t & (WQ - 1);
    int h  = (t / WQ) & (H_ - 1);
    int a  = (t / (WQ * H_)) % A_;
    int b  =  t / (WQ * H_ * A_);
    int w0 = wq * 4;

    int sp4 = (h * W_ + w0) >> 2;

    const float4* cla4 = (const float4*)cla;
    const float4* reg4 = (const float4*)reg;

    int cbase = (b * 2 * A_ + 2 * a) * HW4 + sp4;
    float4 v_c0 = cla4[cbase];
    float4 v_c1 = cla4[cbase + HW4];

    int rbase = (b * 4 * A_ + 4 * a) * HW4 + sp4;
    float4 v_tx = reg4[rbase + 0 * HW4];
    float4 v_ty = reg4[rbase + 1 * HW4];
    float4 v_tw = reg4[rbase + 2 * HW4];
    float4 v_th = reg4[rbase + 3 * HW4];

    // Anchor entries: 4 consecutive float4s, lane-consecutive (L1-hot table).
    const float4* tab = d_anc_tab + a * W_ + w0;
    float4 anca[4] = {tab[0], tab[1], tab[2], tab[3]};

    float c0a[4] = {v_c0.x, v_c0.y, v_c0.z, v_c0.w};
    float c1a[4] = {v_c1.x, v_c1.y, v_c1.z, v_c1.w};
    float txa[4] = {v_tx.x, v_tx.y, v_tx.z, v_tx.w};
    float tya[4] = {v_ty.x, v_ty.y, v_ty.z, v_ty.w};
    float twa[4] = {v_tw.x, v_tw.y, v_tw.z, v_tw.w};
    float tha[4] = {v_th.x, v_th.y, v_th.z, v_th.w};

    float4* my = sOut + tid * 9;   // stride 36 words: conflict-free STS.128

    float f[4][9];
    #pragma unroll
    for (int i = 0; i < 4; i++) {
        float acx = anca[i].x, acy = anca[i].y, aw = anca[i].z, ah = anca[i].w;

        float cxn = fmaf(txa[i], aw, acx);
        float cyn = fmaf(tya[i], ah, acy);
        float wvn = expf(twa[i]) * aw;
        float hvn = expf(tha[i]) * ah;

        float ltxn = cxn - 0.5f * wvn;
        float ltyn = cyn - 0.5f * hvn;
        float rbxn = cxn + 0.5f * wvn;
        float rbyn = cyn + 0.5f * hvn;

        // fg > 0.7  <=>  (c1 - c0) > ln(7/3)
        bool valid = ((c1a[i] - c0a[i]) > LOGIT_THRESH)
                     && (ltxn >= 0.0f) && (ltyn >= 0.0f)
                     && (rbxn <= 1.0f) && (rbyn <= 1.0f);
        float m = valid ? 1.0f : 0.0f;

        f[i][0] = (ltxn * S_) * m;
        f[i][1] = (ltyn * S_) * m;
        f[i][2] = (rbxn * S_) * m;
        f[i][3] = (rbyn * S_) * m;
        f[i][4] = cxn * m;
        f[i][5] = cyn * m;
        f[i][6] = wvn * m;
        f[i][7] = hvn * m;
        f[i][8] = m;
    }

    // Pack 4x9 floats into 9 float4 smem slots (output-linear order).
    my[0] = make_float4(f[0][0], f[0][1], f[0][2], f[0][3]);
    my[1] = make_float4(f[0][4], f[0][5], f[0][6], f[0][7]);
    my[2] = make_float4(f[0][8], f[1][0], f[1][1], f[1][2]);
    my[3] = make_float4(f[1][3], f[1][4], f[1][5], f[1][6]);
    my[4] = make_float4(f[1][7], f[1][8], f[2][0], f[2][1]);
    my[5] = make_float4(f[2][2], f[2][3], f[2][4], f[2][5]);
    my[6] = make_float4(f[2][6], f[2][7], f[2][8], f[3][0]);
    my[7] = make_float4(f[3][1], f[3][2], f[3][3], f[3][4]);
    my[8] = make_float4(f[3][5], f[3][6], f[3][7], f[3][8]);

    __syncthreads();

    // Two independent TMA 1-D bulk stores (tid 0 and tid 1 each own a
    // per-thread bulk group); the halves drain concurrently.
    if (tid < 2) {
        asm volatile("fence.proxy.async.shared::cta;" ::: "memory");
        uint32_t src = smem_u32(sOut + tid * (128 * 9));
        float* dst = out + (size_t)blockIdx.x * (TPB * 36) + tid * (128 * 36);
        asm volatile(
            "cp.async.bulk.global.shared::cta.bulk_group [%0], [%1], %2;"
            :: "l"(dst), "r"(src), "r"((int)HALF_BYTES) : "memory");
        asm volatile("cp.async.bulk.commit_group;" ::: "memory");
        asm volatile("cp.async.bulk.wait_group.read 0;" ::: "memory");
    }
}

extern "C" void kernel_launch(void* const* d_in, const int* in_sizes, int n_in,
                              void* d_out, int out_size) {
    const float* cla    = (const float*)d_in[0];
    const float* reg    = (const float*)d_in[1];
    const float* anchor = (const float*)d_in[2];
    float* out = (float*)d_out;

    build_anchor_tab<<<(A_ * W_ + 127) / 128, 128>>>(anchor);

    int total_vec = B_ * A_ * H_ * (W_ / 4);   // 589824
    proposal_kernel<<<total_vec / TPB, TPB>>>(cla, reg, out);
}

// round 16
// speedup vs baseline: 1.1449x; 1.0619x over previous
#include <cuda_runtime.h>
#include <cstdint>

// Problem constants (fixed by setup_inputs)
#define B_ 16
#define A_ 9
#define H_ 128
#define W_ 128
#define S_ 2048.0f
// sigmoid(d) > 0.7  <=>  d > ln(7/3)
#define LOGIT_THRESH 0.84729786038720363f

#define TPB 128
#define BLK_BYTES (TPB * 9 * 16)   // 18432 B contiguous output per block

// Precomputed anchor table, (a, w) order: (acx, acy, aw, ah). 18 KB, L1/L2-hot.
// (per-block a*w*129 gather: ~9us, R4 vs R5; software spin fusion: +5us, R12.
//  PDL overlaps the two kernels with the HW dependency gate instead.)
__device__ float4 d_anc_tab[A_ * W_];

__global__ void build_anchor_tab(const float* __restrict__ anchor) {
    int t = blockIdx.x * blockDim.x + threadIdx.x;
    if (t < A_ * W_) {
        int a = t / W_;
        int w = t % W_;
        long row = (long)a * w * (W_ + 1);    // idx[a,w] = a*w*(W+1)
        const float* p = anchor + row * 6;
        d_anc_tab[t] = make_float4(p[2], p[3], p[4], p[5]);
    }
    // Make table writes visible, then allow the dependent grid to pass its
    // cudaGridDependencySynchronize().
    __threadfence();
    cudaTriggerProgrammaticLaunchCompletion();
}

__device__ __forceinline__ uint32_t smem_u32(const void* p) {
    uint32_t a;
    asm("{ .reg .u64 t; cvta.to.shared.u64 t, %1; cvt.u32.u64 %0, t; }"
        : "=r"(a) : "l"(p));
    return a;
}

// R9 structure (best measured). Launched with programmatic stream
// serialization: this grid ramps up and issues its 6 input LDG.128s while
// build_anchor_tab is still running; it blocks only at the gridsync before
// reading the table.
__global__ __launch_bounds__(TPB) void proposal_kernel(
    const float* __restrict__ cla,
    const float* __restrict__ reg,
    float* __restrict__ out)
{
    // Output staging: TPB threads x 9 float4 slots, output-linear layout.
    __shared__ __align__(128) float4 sOut[TPB * 9];   // 18432 B

    const int WQ  = W_ / 4;         // 32
    const int HW4 = (H_ * W_) / 4;  // 4096 float4 per channel plane

    int tid = threadIdx.x;
    int t = blockIdx.x * TPB + tid;
    int wq = t & (WQ - 1);                    // == tid & 31
    int h  = (t / WQ) & (H_ - 1);
    int a  = (t / (WQ * H_)) % A_;            // uniform within a block
    int b  =  t / (WQ * H_ * A_);
    int w0 = wq * 4;

    int sp4 = (h * W_ + w0) >> 2;

    const float4* cla4 = (const float4*)cla;
    const float4* reg4 = (const float4*)reg;

    // Input loads first: independent of the anchor table, they overlap the
    // prologue kernel still draining.
    int cbase = (b * 2 * A_ + 2 * a) * HW4 + sp4;
    float4 v_c0 = cla4[cbase];
    float4 v_c1 = cla4[cbase + HW4];

    int rbase = (b * 4 * A_ + 4 * a) * HW4 + sp4;
    float4 v_tx = reg4[rbase + 0 * HW4];
    float4 v_ty = reg4[rbase + 1 * HW4];
    float4 v_tw = reg4[rbase + 2 * HW4];
    float4 v_th = reg4[rbase + 3 * HW4];

    // Wait for build_anchor_tab's completion trigger (table visible after).
    cudaGridDependencySynchronize();

    // Anchor entries: 4 consecutive float4s, lane-consecutive (L1-hot table).
    const float4* tab = d_anc_tab + a * W_ + w0;
    float4 anca[4] = {tab[0], tab[1], tab[2], tab[3]};

    float c0a[4] = {v_c0.x, v_c0.y, v_c0.z, v_c0.w};
    float c1a[4] = {v_c1.x, v_c1.y, v_c1.z, v_c1.w};
    float txa[4] = {v_tx.x, v_tx.y, v_tx.z, v_tx.w};
    float tya[4] = {v_ty.x, v_ty.y, v_ty.z, v_ty.w};
    float twa[4] = {v_tw.x, v_tw.y, v_tw.z, v_tw.w};
    float tha[4] = {v_th.x, v_th.y, v_th.z, v_th.w};

    float4* my = sOut + tid * 9;   // stride 36 words: conflict-free STS.128

    float f[4][9];
    #pragma unroll
    for (int i = 0; i < 4; i++) {
        float acx = anca[i].x, acy = anca[i].y, aw = anca[i].z, ah = anca[i].w;

        float cxn = fmaf(txa[i], aw, acx);
        float cyn = fmaf(tya[i], ah, acy);
        float wvn = expf(twa[i]) * aw;
        float hvn = expf(tha[i]) * ah;

        float ltxn = cxn - 0.5f * wvn;
        float ltyn = cyn - 0.5f * hvn;
        float rbxn = cxn + 0.5f * wvn;
        float rbyn = cyn + 0.5f * hvn;

        // fg > 0.7  <=>  (c1 - c0) > ln(7/3)
        bool valid = ((c1a[i] - c0a[i]) > LOGIT_THRESH)
                     && (ltxn >= 0.0f) && (ltyn >= 0.0f)
                     && (rbxn <= 1.0f) && (rbyn <= 1.0f);
        float m = valid ? 1.0f : 0.0f;

        f[i][0] = (ltxn * S_) * m;
        f[i][1] = (ltyn * S_) * m;
        f[i][2] = (rbxn * S_) * m;
        f[i][3] = (rbyn * S_) * m;
        f[i][4] = cxn * m;
        f[i][5] = cyn * m;
        f[i][6] = wvn * m;
        f[i][7] = hvn * m;
        f[i][8] = m;
    }

    // Pack 4x9 floats into 9 float4 smem slots (output-linear order).
    my[0] = make_float4(f[0][0], f[0][1], f[0][2], f[0][3]);
    my[1] = make_float4(f[0][4], f[0][5], f[0][6], f[0][7]);
    my[2] = make_float4(f[0][8], f[1][0], f[1][1], f[1][2]);
    my[3] = make_float4(f[1][3], f[1][4], f[1][5], f[1][6]);
    my[4] = make_float4(f[1][7], f[1][8], f[2][0], f[2][1]);
    my[5] = make_float4(f[2][2], f[2][3], f[2][4], f[2][5]);
    my[6] = make_float4(f[2][6], f[2][7], f[2][8], f[3][0]);
    my[7] = make_float4(f[3][1], f[3][2], f[3][3], f[3][4]);
    my[8] = make_float4(f[3][5], f[3][6], f[3][7], f[3][8]);

    __syncthreads();

    // Single TMA 1-D bulk store of the block's contiguous 18432B output.
    if (tid == 0) {
        asm volatile("fence.proxy.async.shared::cta;" ::: "memory");
        uint32_t src = smem_u32(sOut);
        float* dst = out + (size_t)blockIdx.x * (TPB * 36);
        asm volatile(
            "cp.async.bulk.global.shared::cta.bulk_group [%0], [%1], %2;"
            :: "l"(dst), "r"(src), "r"((int)BLK_BYTES) : "memory");
        asm volatile("cp.async.bulk.commit_group;" ::: "memory");
        asm volatile("cp.async.bulk.wait_group.read 0;" ::: "memory");
    }
}

extern "C" void kernel_launch(void* const* d_in, const int* in_sizes, int n_in,
                              void* d_out, int out_size) {
    const float* cla    = (const float*)d_in[0];
    const float* reg    = (const float*)d_in[1];
    const float* anchor = (const float*)d_in[2];
    float* out = (float*)d_out;

    build_anchor_tab<<<(A_ * W_ + 127) / 128, 128>>>(anchor);

    // Launch main kernel with programmatic dependent launch: it may start
    // while build_anchor_tab runs; cudaGridDependencySynchronize() inside
    // gates the table read.
    cudaLaunchConfig_t cfg = {};
    cfg.gridDim  = dim3(B_ * A_ * H_ * (W_ / 4) / TPB);   // 4608
    cfg.blockDim = dim3(TPB);
    cudaLaunchAttribute attrs[1];
    attrs[0].id = cudaLaunchAttributeProgrammaticStreamSerialization;
    attrs[0].val.programmaticStreamSerializationAllowed = 1;
    cfg.attrs = attrs;
    cfg.numAttrs = 1;
    cudaLaunchKernelEx(&cfg, proposal_kernel, cla, reg, out);
}